// round 10
// baseline (speedup 1.0000x reference)
#include <cuda_runtime.h>
#include <math.h>

#define T_ 512
#define B_ 64
#define I_ 128
#define H_ 512
#define O_ 128
#define K_ 32
#define IH 640
#define N3 1536
#define NCTA 128

typedef unsigned long long u64;

// ---------------- device scratch (allocation-free rule) ----------------
__device__ __align__(128) float g_Hall[(size_t)(T_ + 1) * B_ * H_];   // [t][b][h] (output GEMM)
__device__ __align__(128) float g_HallT[(size_t)(T_ + 1) * H_ * B_];  // [t][h][b] (staging)
__device__ __align__(128) float g_XT[(size_t)T_ * I_ * B_];           // [t][i][b]
__device__ __align__(128) float g_WAll[IH * N3];                      // [ng][640][48]
__device__ float g_bn[N3];                                            // [h*3+g]
__device__ float g_wd[K_ * H_];                                       // [j][h]
__device__ unsigned g_flag[(T_ + 1) * 4 * 32];                        // [t][bg][ng]

// ---------------- helpers ----------------
__device__ __forceinline__ void fma2(u64 &d, u64 a, u64 b) {
    asm("fma.rn.f32x2 %0, %1, %2, %0;" : "+l"(d) : "l"(a), "l"(b));
}
__device__ __forceinline__ u64 dup2(float w) {
    u64 r; asm("mov.b64 %0, {%1, %1};" : "=l"(r) : "f"(w)); return r;
}
__device__ __forceinline__ u64 pk2(float a, float b) {
    u64 r; asm("mov.b64 %0, {%1, %2};" : "=l"(r) : "f"(a), "f"(b)); return r;
}
__device__ __forceinline__ float sigmoidf_(float x) { return 1.f / (1.f + expf(-x)); }
__device__ __forceinline__ void wait_flag(const unsigned *p) {
    unsigned v;
    asm volatile("ld.acquire.gpu.global.u32 %0, [%1];" : "=r"(v) : "l"(p) : "memory");
    while (v == 0u) {
        __nanosleep(32);
        asm volatile("ld.acquire.gpu.global.u32 %0, [%1];" : "=r"(v) : "l"(p) : "memory");
    }
}
__device__ __forceinline__ void set_flag(unsigned *p) {
    asm volatile("st.release.gpu.global.u32 [%0], %1;" :: "l"(p), "r"(1u) : "memory");
}

// ---------------- prep ----------------
__global__ void prep_kernel(const float *__restrict__ Wi, const float *__restrict__ bi,
                            const float *__restrict__ Wo, const float *__restrict__ bo,
                            const float *__restrict__ Wc, const float *__restrict__ bc,
                            const float *__restrict__ dv) {
    int idx = blockIdx.x * blockDim.x + threadIdx.x;
    if (idx < IH * H_) {     // pack all 640 k rows per ng slice, gate-interleaved
        int k = idx >> 9, h = idx & 511;
        float *p = g_WAll + (size_t)(h >> 4) * (IH * 48) + (size_t)k * 48 + (h & 15) * 3;
        p[0] = Wi[idx]; p[1] = Wo[idx]; p[2] = Wc[idx];
    }
    if (idx < H_) {
        g_bn[idx * 3 + 0] = bi[idx];
        g_bn[idx * 3 + 1] = bo[idx];
        g_bn[idx * 3 + 2] = bc[idx];
        float d = 0.5f * sigmoidf_(dv[idx]);
        float v = 1.f;
        for (int i = 0; i < K_; i++) {          // v_{i+1} = v_i*(i-d)/(i+1); wd[K-1-i]=v_{i+1}
            v *= ((float)i - d) / ((float)i + 1.f);
            g_wd[(K_ - 1 - i) * H_ + idx] = v;
        }
    }
    if (idx < B_ * H_) g_HallT[idx] = 0.f;                    // h_0 = 0
    if (idx < (T_ + 1) * 4 * 32) g_flag[idx] = 0u;            // reset flags each launch
}

// ---------------- input transpose: [t][b][i] -> g_XT [t][i][b] ----------------
__global__ void transpose_x(const float *__restrict__ in) {
    __shared__ float ts[I_][B_ + 1];
    int t = blockIdx.x;
    const float *src = in + (size_t)t * B_ * I_;
    for (int idx = threadIdx.x; idx < B_ * I_; idx += 256) {
        int b = idx >> 7, i = idx & 127;
        ts[i][b] = src[idx];
    }
    __syncthreads();
    float *dst = g_XT + (size_t)t * I_ * B_;
    for (int idx = threadIdx.x; idx < B_ * I_; idx += 256) {
        int i = idx >> 6, b = idx & 63;
        dst[idx] = ts[i][b];
    }
}

// ---------------- fp32 GEMM + bias (output projection) ----------------
__global__ void __launch_bounds__(256) gemm_bias(const float *__restrict__ A,
                                                 const float *__restrict__ Bm,
                                                 const float *__restrict__ bias,
                                                 float *__restrict__ C, int N, int Kd) {
    __shared__ float As[16 * 130];
    __shared__ u64   Bs[16 * 64];
    int tid = threadIdx.x;
    int m0 = blockIdx.x * 128, n0 = blockIdx.y * 64;
    int tx = tid & 15, ty = tid >> 4;
    int ar = tid >> 1, ac = (tid & 1) * 8;
    int bk = tid >> 4, bn = (tid & 15) * 4;

    u64 acc[4][4];
#pragma unroll
    for (int p = 0; p < 4; p++)
#pragma unroll
        for (int i = 0; i < 4; i++) acc[p][i] = 0ull;

    const float *Arow = A + (size_t)(m0 + ar) * Kd + ac;
    const float *Brow = Bm + (size_t)bk * N + n0 + bn;
    float4 av0 = *(const float4 *)(Arow);
    float4 av1 = *(const float4 *)(Arow + 4);
    float4 bv  = *(const float4 *)(Brow);

    for (int kc = 0; kc < Kd; kc += 16) {
        __syncthreads();
        {
            float a0s[4] = {av0.x, av0.y, av0.z, av0.w};
            float a1s[4] = {av1.x, av1.y, av1.z, av1.w};
#pragma unroll
            for (int q = 0; q < 4; q++) As[(ac + q) * 130 + ar] = a0s[q];
#pragma unroll
            for (int q = 0; q < 4; q++) As[(ac + 4 + q) * 130 + ar] = a1s[q];
            float bvs[4] = {bv.x, bv.y, bv.z, bv.w};
#pragma unroll
            for (int q = 0; q < 4; q++) Bs[bk * 64 + bn + q] = dup2(bvs[q]);
        }
        __syncthreads();
        if (kc + 16 < Kd) {
            av0 = *(const float4 *)(Arow + kc + 16);
            av1 = *(const float4 *)(Arow + kc + 20);
            bv  = *(const float4 *)(Brow + (size_t)(kc + 16) * N);
        }
#pragma unroll
        for (int kk = 0; kk < 16; kk++) {
            u64 a0 = *(const u64 *)&As[kk * 130 + ty * 8 + 0];
            u64 a1 = *(const u64 *)&As[kk * 130 + ty * 8 + 2];
            u64 a2 = *(const u64 *)&As[kk * 130 + ty * 8 + 4];
            u64 a3 = *(const u64 *)&As[kk * 130 + ty * 8 + 6];
            u64 b0 = Bs[kk * 64 + tx],      b1 = Bs[kk * 64 + tx + 16];
            u64 b2 = Bs[kk * 64 + tx + 32], b3 = Bs[kk * 64 + tx + 48];
            fma2(acc[0][0], a0, b0); fma2(acc[0][1], a0, b1);
            fma2(acc[0][2], a0, b2); fma2(acc[0][3], a0, b3);
            fma2(acc[1][0], a1, b0); fma2(acc[1][1], a1, b1);
            fma2(acc[1][2], a1, b2); fma2(acc[1][3], a1, b3);
            fma2(acc[2][0], a2, b0); fma2(acc[2][1], a2, b1);
            fma2(acc[2][2], a2, b2); fma2(acc[2][3], a2, b3);
            fma2(acc[3][0], a3, b0); fma2(acc[3][1], a3, b1);
            fma2(acc[3][2], a3, b2); fma2(acc[3][3], a3, b3);
        }
    }
#pragma unroll
    for (int p = 0; p < 4; p++) {
        int m = m0 + ty * 8 + p * 2;
#pragma unroll
        for (int i = 0; i < 4; i++) {
            int n = n0 + tx + 16 * i;
            float lo = __uint_as_float((unsigned)(acc[p][i] & 0xffffffffull));
            float hi = __uint_as_float((unsigned)(acc[p][i] >> 32));
            float bb = bias[n];
            C[(size_t)m * N + n] = lo + bb;
            C[(size_t)(m + 1) * N + n] = hi + bb;
        }
    }
}

// ---------------- persistent recurrent kernel: 128 CTAs = 4 bg x 32 ng ----------------
// SMEM floats: Whs[0,30720)  h2s[30720,42240) (640x9 u64)  ring[42240,50432)
//              red[50432,56576) (3072 u64)  wds[56576,57088)
#define SMEM_FLOATS 57088
#define SMEM_BYTES (SMEM_FLOATS * 4)

#define GEMM16(BASEROW)                                                   \
    { const u64 *hr = h2s + (size_t)(BASEROW) * 9 + bpH * 4;              \
      const float *wr = Whs + (BASEROW) * 48 + hq * 3;                    \
      _Pragma("unroll")                                                   \
      for (int kk_ = 0; kk_ < 16; kk_++) {                                \
          u64 h0 = hr[0], h1 = hr[1], h2v = hr[2], h3v = hr[3];           \
          u64 w0 = dup2(wr[0]), w1 = dup2(wr[1]), w2 = dup2(wr[2]);       \
          fma2(a00, h0, w0);  fma2(a01, h0, w1);  fma2(a02, h0, w2);      \
          fma2(a10, h1, w0);  fma2(a11, h1, w1);  fma2(a12, h1, w2);      \
          fma2(a20, h2v, w0); fma2(a21, h2v, w1); fma2(a22, h2v, w2);     \
          fma2(a30, h3v, w0); fma2(a31, h3v, w1); fma2(a32, h3v, w2);     \
          hr += 9; wr += 48; } }

#define STS4(BASEROW, V0, V1)                                             \
    { u64 *d_ = h2s + (size_t)(BASEROW) * 9 + half * 4;                   \
      d_[0] = pk2((V0).x, (V0).y); d_[1] = pk2((V0).z, (V0).w);           \
      d_[2] = pk2((V1).x, (V1).y); d_[3] = pk2((V1).z, (V1).w); }

__global__ void __launch_bounds__(256, 1) recurrent_kernel(float *__restrict__ dout) {
    extern __shared__ float sm[];
    float *Whs = sm;
    u64 *h2s = (u64 *)(sm + 30720);
    float *ring = sm + 42240;
    u64 *red = (u64 *)(sm + 50432);
    const float *redf = sm + 50432;
    float *wds = sm + 56576;

    int tid = threadIdx.x;
    int bid = blockIdx.x;
    int bg = bid >> 5, ng = bid & 31;
    int bbase = bg * 16, hbase = ng * 16;

    // weight slice [640][48]
    {
        const float4 *src = (const float4 *)(g_WAll + (size_t)ng * (IH * 48));
        float4 *dst = (float4 *)Whs;
        for (int i = tid; i < IH * 48 / 4; i += 256) dst[i] = src[i];
    }
    for (int i = tid; i < K_ * 16; i += 256)
        wds[i] = g_wd[(i >> 4) * H_ + hbase + (i & 15)];
    for (int i = tid; i < K_ * 256; i += 256) ring[i] = 0.f;
    __syncthreads();

    // GEMM role
    int ks = tid >> 5, lane = tid & 31;
    int bpH = lane >> 4, hq = lane & 15;
    int kl = lane >> 1, half = lane & 1;
    // elementwise role
    int h_l = tid & 15, b_l = tid >> 4;
    int bp = b_l >> 1, comp = b_l & 1;

    float bs0 = g_bn[(hbase + h_l) * 3 + 0];
    float bs1 = g_bn[(hbase + h_l) * 3 + 1];
    float bs2 = g_bn[(hbase + h_l) * 3 + 2];

    for (int t = 0; t < T_; t++) {
        u64 a00 = 0, a01 = 0, a02 = 0, a10 = 0, a11 = 0, a12 = 0;
        u64 a20 = 0, a21 = 0, a22 = 0, a30 = 0, a31 = 0, a32 = 0;

        // --- x chunk (always ready): stage + GEMM, prefetch h-chunk 0 under it ---
        {
            const float4 *xs = (const float4 *)(g_XT + (size_t)t * (I_ * B_) +
                                                (size_t)(ks * 16 + kl) * B_ + bbase + half * 8);
            float4 v0 = xs[0], v1 = xs[1];
            STS4(ks * 16 + kl, v0, v1);
        }
        __syncwarp();
        float4 s0, s1;
        {
            if (t > 0) wait_flag(g_flag + ((size_t)t * 4 + bg) * 32 + (ks * 4 + 0));
            const float4 *hs = (const float4 *)(g_HallT + (size_t)t * (H_ * B_) +
                                                (size_t)(ks * 64 + kl) * B_ + bbase + half * 8);
            s0 = hs[0]; s1 = hs[1];
        }
        GEMM16(ks * 16);

        // --- 4 h chunks, software-pipelined ---
#pragma unroll
        for (int c = 0; c < 4; c++) {
            STS4(128 + ks * 64 + c * 16 + kl, s0, s1);
            __syncwarp();
            if (c < 3) {
                if (t > 0) wait_flag(g_flag + ((size_t)t * 4 + bg) * 32 + (ks * 4 + c + 1));
                const float4 *hs = (const float4 *)(g_HallT + (size_t)t * (H_ * B_) +
                                                    (size_t)(ks * 64 + (c + 1) * 16 + kl) * B_ +
                                                    bbase + half * 8);
                s0 = hs[0]; s1 = hs[1];
            }
            GEMM16(128 + ks * 64 + c * 16);
        }

        // partial writes
        {
            u64 *rp = red + ((size_t)(ks * 8 + bpH * 4) * 16 + hq) * 3;
            rp[0] = a00;  rp[1] = a01;  rp[2] = a02;
            rp[48] = a10; rp[49] = a11; rp[50] = a12;
            rp[96] = a20; rp[97] = a21; rp[98] = a22;
            rp[144] = a30; rp[145] = a31; rp[146] = a32;
        }
        __syncthreads();

        // elementwise per (b_l,h_l)
        float p0 = bs0, p1 = bs1, p2 = bs2;
#pragma unroll
        for (int s = 0; s < 8; s++) {
            int base = (((s * 8 + bp) * 16 + h_l) * 3) * 2 + comp;
            p0 += redf[base];
            p1 += redf[base + 2];
            p2 += redf[base + 4];
        }
        float gi = sigmoidf_(p0);
        float go = sigmoidf_(p1);
        float gc = tanhf(p2);
        float conv = 0.f;
        int rbase = b_l * 16 + h_l;
#pragma unroll
        for (int j = 0; j < K_; j++)
            conv += wds[j * 16 + h_l] * ring[(((t + j) & 31) << 8) + rbase];
        float c = gi * gc - conv;
        ring[((t & 31) << 8) + rbase] = c;
        float hn = go * tanhf(c);
        g_HallT[((size_t)(t + 1) * H_ + hbase + h_l) * B_ + bbase + b_l] = hn;
        g_Hall[((size_t)(t + 1) * B_ + bbase + b_l) * H_ + hbase + h_l] = hn;
        if (t == T_ - 1)
            dout[(size_t)T_ * B_ * O_ + (size_t)(bbase + b_l) * H_ + hbase + h_l] = hn;

        __syncthreads();
        if (tid == 0) set_flag(g_flag + ((size_t)(t + 1) * 4 + bg) * 32 + ng);
    }

    // epilogue: hc_last = ring (slot j == hc_last[j] since 480 % 32 == 0)
    {
        const size_t HC0 = (size_t)T_ * B_ * O_ + (size_t)B_ * H_;
#pragma unroll
        for (int j = 0; j < K_; j++)
            dout[HC0 + ((size_t)j * B_ + bbase + b_l) * H_ + hbase + h_l] =
                ring[(j << 8) + b_l * 16 + h_l];
    }
}

// ---------------- launch ----------------
extern "C" void kernel_launch(void* const* d_in, const int* in_sizes, int n_in,
                              void* d_out, int out_size) {
    const float *inputs = (const float *)d_in[0];
    const float *Wi = (const float *)d_in[1];
    const float *bi = (const float *)d_in[2];
    const float *Wo = (const float *)d_in[3];
    const float *bo = (const float *)d_in[4];
    const float *Wc = (const float *)d_in[5];
    const float *bc = (const float *)d_in[6];
    const float *Wout = (const float *)d_in[7];
    const float *bout = (const float *)d_in[8];
    const float *dv = (const float *)d_in[9];
    float *out = (float *)d_out;

    float *pHall = nullptr;
    cudaGetSymbolAddress((void **)&pHall, g_Hall);
    cudaFuncSetAttribute(recurrent_kernel, cudaFuncAttributeMaxDynamicSharedMemorySize,
                         SMEM_BYTES);

    // 1) pack weights / biases / frac-diff weights, zero h_0 + flags
    prep_kernel<<<1280, 256>>>(Wi, bi, Wo, bo, Wc, bc, dv);
    // 2) transpose inputs -> [t][i][b]
    transpose_x<<<T_, 256>>>(inputs);
    // 3) serial recurrence (persistent, flag-pipelined; x-projection fused in)
    recurrent_kernel<<<NCTA, 256, SMEM_BYTES>>>(out);
    // 4) outputs: [T*B,512] @ [512,128] + bias -> d_out[0 : T*B*O)
    gemm_bias<<<dim3((T_ * B_) / 128, O_ / 64), 256>>>(pHall + B_ * H_, Wout, bout, out, O_, H_);
}

// round 12
// speedup vs baseline: 1.5577x; 1.5577x over previous
#include <cuda_runtime.h>
#include <math.h>

#define T_ 512
#define B_ 64
#define I_ 128
#define H_ 512
#define O_ 128
#define K_ 32
#define IH 640
#define N3 1536
#define NCTA 128

typedef unsigned long long u64;

// ---------------- device scratch (allocation-free rule) ----------------
__device__ __align__(128) float g_Hall[(size_t)(T_ + 1) * B_ * H_];   // [t][b][h] (output GEMM)
__device__ __align__(128) float g_HallT[(size_t)(T_ + 1) * H_ * B_];  // [t][h][b] (staging)
__device__ __align__(128) float g_XT[(size_t)T_ * I_ * B_];           // [t][i][b]
__device__ __align__(128) float g_WAll[IH * N3];                      // [ng][640][48]
__device__ float g_bn[N3];                                            // [h*3+g]
__device__ float g_wd[K_ * H_];                                       // [j][h]
__device__ unsigned g_cnt2[4 * 32];                                   // per-bg arrive counter (128B apart)
__device__ unsigned g_gen2[4 * 32];                                   // per-bg generation word

// ---------------- helpers ----------------
__device__ __forceinline__ void fma2(u64 &d, u64 a, u64 b) {
    asm("fma.rn.f32x2 %0, %1, %2, %0;" : "+l"(d) : "l"(a), "l"(b));
}
__device__ __forceinline__ u64 dup2(float w) {
    u64 r; asm("mov.b64 %0, {%1, %1};" : "=l"(r) : "f"(w)); return r;
}
__device__ __forceinline__ u64 pk2(float a, float b) {
    u64 r; asm("mov.b64 %0, {%1, %2};" : "=l"(r) : "f"(a), "f"(b)); return r;
}
__device__ __forceinline__ float sigmoidf_(float x) { return 1.f / (1.f + expf(-x)); }

// ---------------- prep ----------------
__global__ void prep_kernel(const float *__restrict__ Wi, const float *__restrict__ bi,
                            const float *__restrict__ Wo, const float *__restrict__ bo,
                            const float *__restrict__ Wc, const float *__restrict__ bc,
                            const float *__restrict__ dv) {
    int idx = blockIdx.x * blockDim.x + threadIdx.x;
    if (idx < IH * H_) {     // pack all 640 k rows per ng slice, gate-interleaved
        int k = idx >> 9, h = idx & 511;
        float *p = g_WAll + (size_t)(h >> 4) * (IH * 48) + (size_t)k * 48 + (h & 15) * 3;
        p[0] = Wi[idx]; p[1] = Wo[idx]; p[2] = Wc[idx];
    }
    if (idx < H_) {
        g_bn[idx * 3 + 0] = bi[idx];
        g_bn[idx * 3 + 1] = bo[idx];
        g_bn[idx * 3 + 2] = bc[idx];
        float d = 0.5f * sigmoidf_(dv[idx]);
        float v = 1.f;
        for (int i = 0; i < K_; i++) {          // v_{i+1} = v_i*(i-d)/(i+1); wd[K-1-i]=v_{i+1}
            v *= ((float)i - d) / ((float)i + 1.f);
            g_wd[(K_ - 1 - i) * H_ + idx] = v;
        }
    }
    if (idx < B_ * H_) g_HallT[idx] = 0.f;      // h_0 = 0
    if (idx < 4 * 32) { g_cnt2[idx] = 0u; g_gen2[idx] = 0u; }   // reset barriers each launch
}

// ---------------- input transpose: [t][b][i] -> g_XT [t][i][b] ----------------
__global__ void transpose_x(const float *__restrict__ in) {
    __shared__ float ts[I_][B_ + 1];
    int t = blockIdx.x;
    const float *src = in + (size_t)t * B_ * I_;
    for (int idx = threadIdx.x; idx < B_ * I_; idx += 256) {
        int b = idx >> 7, i = idx & 127;
        ts[i][b] = src[idx];
    }
    __syncthreads();
    float *dst = g_XT + (size_t)t * I_ * B_;
    for (int idx = threadIdx.x; idx < B_ * I_; idx += 256) {
        int i = idx >> 6, b = idx & 63;
        dst[idx] = ts[i][b];
    }
}

// ---------------- fp32 GEMM + bias (output projection) ----------------
__global__ void __launch_bounds__(256) gemm_bias(const float *__restrict__ A,
                                                 const float *__restrict__ Bm,
                                                 const float *__restrict__ bias,
                                                 float *__restrict__ C, int N, int Kd) {
    __shared__ float As[16 * 130];
    __shared__ u64   Bs[16 * 64];
    int tid = threadIdx.x;
    int m0 = blockIdx.x * 128, n0 = blockIdx.y * 64;
    int tx = tid & 15, ty = tid >> 4;
    int ar = tid >> 1, ac = (tid & 1) * 8;
    int bk = tid >> 4, bn = (tid & 15) * 4;

    u64 acc[4][4];
#pragma unroll
    for (int p = 0; p < 4; p++)
#pragma unroll
        for (int i = 0; i < 4; i++) acc[p][i] = 0ull;

    const float *Arow = A + (size_t)(m0 + ar) * Kd + ac;
    const float *Brow = Bm + (size_t)bk * N + n0 + bn;
    float4 av0 = *(const float4 *)(Arow);
    float4 av1 = *(const float4 *)(Arow + 4);
    float4 bv  = *(const float4 *)(Brow);

    for (int kc = 0; kc < Kd; kc += 16) {
        __syncthreads();
        {
            float a0s[4] = {av0.x, av0.y, av0.z, av0.w};
            float a1s[4] = {av1.x, av1.y, av1.z, av1.w};
#pragma unroll
            for (int q = 0; q < 4; q++) As[(ac + q) * 130 + ar] = a0s[q];
#pragma unroll
            for (int q = 0; q < 4; q++) As[(ac + 4 + q) * 130 + ar] = a1s[q];
            float bvs[4] = {bv.x, bv.y, bv.z, bv.w};
#pragma unroll
            for (int q = 0; q < 4; q++) Bs[bk * 64 + bn + q] = dup2(bvs[q]);
        }
        __syncthreads();
        if (kc + 16 < Kd) {
            av0 = *(const float4 *)(Arow + kc + 16);
            av1 = *(const float4 *)(Arow + kc + 20);
            bv  = *(const float4 *)(Brow + (size_t)(kc + 16) * N);
        }
#pragma unroll
        for (int kk = 0; kk < 16; kk++) {
            u64 a0 = *(const u64 *)&As[kk * 130 + ty * 8 + 0];
            u64 a1 = *(const u64 *)&As[kk * 130 + ty * 8 + 2];
            u64 a2 = *(const u64 *)&As[kk * 130 + ty * 8 + 4];
            u64 a3 = *(const u64 *)&As[kk * 130 + ty * 8 + 6];
            u64 b0 = Bs[kk * 64 + tx],      b1 = Bs[kk * 64 + tx + 16];
            u64 b2 = Bs[kk * 64 + tx + 32], b3 = Bs[kk * 64 + tx + 48];
            fma2(acc[0][0], a0, b0); fma2(acc[0][1], a0, b1);
            fma2(acc[0][2], a0, b2); fma2(acc[0][3], a0, b3);
            fma2(acc[1][0], a1, b0); fma2(acc[1][1], a1, b1);
            fma2(acc[1][2], a1, b2); fma2(acc[1][3], a1, b3);
            fma2(acc[2][0], a2, b0); fma2(acc[2][1], a2, b1);
            fma2(acc[2][2], a2, b2); fma2(acc[2][3], a2, b3);
            fma2(acc[3][0], a3, b0); fma2(acc[3][1], a3, b1);
            fma2(acc[3][2], a3, b2); fma2(acc[3][3], a3, b3);
        }
    }
#pragma unroll
    for (int p = 0; p < 4; p++) {
        int m = m0 + ty * 8 + p * 2;
#pragma unroll
        for (int i = 0; i < 4; i++) {
            int n = n0 + tx + 16 * i;
            float lo = __uint_as_float((unsigned)(acc[p][i] & 0xffffffffull));
            float hi = __uint_as_float((unsigned)(acc[p][i] >> 32));
            float bb = bias[n];
            C[(size_t)m * N + n] = lo + bb;
            C[(size_t)(m + 1) * N + n] = hi + bb;
        }
    }
}

// ---------------- persistent recurrent kernel: 128 CTAs = 4 bg x 32 ng ----------------
// SMEM floats: Whs[0,30720)  h2s[30720,42240) (640x9 u64)  ring[42240,50432)
//              red[50432,56576) (3072 u64)  wds[56576,57088)
#define SMEM_FLOATS 57088
#define SMEM_BYTES (SMEM_FLOATS * 4)

#define GEMM16(BASEROW)                                                   \
    { const u64 *hr = h2s + (size_t)(BASEROW) * 9 + bpH * 4;              \
      const float *wr = Whs + (BASEROW) * 48 + hq * 3;                    \
      _Pragma("unroll")                                                   \
      for (int kk_ = 0; kk_ < 16; kk_++) {                                \
          u64 h0 = hr[0], h1 = hr[1], h2v = hr[2], h3v = hr[3];           \
          u64 w0 = dup2(wr[0]), w1 = dup2(wr[1]), w2 = dup2(wr[2]);       \
          fma2(a00, h0, w0);  fma2(a01, h0, w1);  fma2(a02, h0, w2);      \
          fma2(a10, h1, w0);  fma2(a11, h1, w1);  fma2(a12, h1, w2);      \
          fma2(a20, h2v, w0); fma2(a21, h2v, w1); fma2(a22, h2v, w2);     \
          fma2(a30, h3v, w0); fma2(a31, h3v, w1); fma2(a32, h3v, w2);     \
          hr += 9; wr += 48; } }

#define STS4(BASEROW, V0, V1)                                             \
    { u64 *d_ = h2s + (size_t)(BASEROW) * 9 + half * 4;                   \
      d_[0] = pk2((V0).x, (V0).y); d_[1] = pk2((V0).z, (V0).w);           \
      d_[2] = pk2((V1).x, (V1).y); d_[3] = pk2((V1).z, (V1).w); }

__global__ void __launch_bounds__(256, 1) recurrent_kernel(float *__restrict__ dout) {
    extern __shared__ float sm[];
    float *Whs = sm;
    u64 *h2s = (u64 *)(sm + 30720);
    float *ring = sm + 42240;
    u64 *red = (u64 *)(sm + 50432);
    const float *redf = sm + 50432;
    float *wds = sm + 56576;

    int tid = threadIdx.x;
    int bid = blockIdx.x;
    int bg = bid >> 5, ng = bid & 31;
    int bbase = bg * 16, hbase = ng * 16;

    // weight slice [640][48]
    {
        const float4 *src = (const float4 *)(g_WAll + (size_t)ng * (IH * 48));
        float4 *dst = (float4 *)Whs;
        for (int i = tid; i < IH * 48 / 4; i += 256) dst[i] = src[i];
    }
    for (int i = tid; i < K_ * 16; i += 256)
        wds[i] = g_wd[(i >> 4) * H_ + hbase + (i & 15)];
    for (int i = tid; i < K_ * 256; i += 256) ring[i] = 0.f;
    __syncthreads();

    // GEMM role
    int ks = tid >> 5, lane = tid & 31;
    int bpH = lane >> 4, hq = lane & 15;
    int kl = lane >> 1, half = lane & 1;
    // elementwise role
    int h_l = tid & 15, b_l = tid >> 4;
    int bp = b_l >> 1, comp = b_l & 1;

    float bs0 = g_bn[(hbase + h_l) * 3 + 0];
    float bs1 = g_bn[(hbase + h_l) * 3 + 1];
    float bs2 = g_bn[(hbase + h_l) * 3 + 2];

    unsigned *pcnt = g_cnt2 + bg * 32;
    unsigned *pgen = g_gen2 + bg * 32;
    int rbase = b_l * 16 + h_l;

    for (int t = 0; t < T_; t++) {
        // ---- pre-barrier slack work: frac-diff conv (CTA-local ring) ----
        float conv = 0.f;
#pragma unroll
        for (int j = 0; j < K_; j++)
            conv += wds[j * 16 + h_l] * ring[(((t + j) & 31) << 8) + rbase];

        // ---- pre-barrier slack work: x chunk stage + GEMM (rows ks*16..+16) ----
        u64 a00 = 0, a01 = 0, a02 = 0, a10 = 0, a11 = 0, a12 = 0;
        u64 a20 = 0, a21 = 0, a22 = 0, a30 = 0, a31 = 0, a32 = 0;
        {
            const float4 *xs = (const float4 *)(g_XT + (size_t)t * (I_ * B_) +
                                                (size_t)(ks * 16 + kl) * B_ + bbase + half * 8);
            float4 v0 = xs[0], v1 = xs[1];
            STS4(ks * 16 + kl, v0, v1);
        }
        __syncwarp();
        GEMM16(ks * 16);

        // ---- per-bg barrier wait: gen[bg] >= t (h_t published) ----
        if (t > 0 && tid == 0) {
            unsigned v;
            asm volatile("ld.acquire.gpu.global.u32 %0, [%1];" : "=r"(v) : "l"(pgen) : "memory");
            while (v < (unsigned)t) {
                __nanosleep(32);
                asm volatile("ld.acquire.gpu.global.u32 %0, [%1];" : "=r"(v) : "l"(pgen) : "memory");
            }
        }
        __syncthreads();

        // ---- h stage + GEMM, 4 chunks software-pipelined (warp-local rows) ----
        float4 s0, s1;
        {
            const float4 *hs = (const float4 *)(g_HallT + (size_t)t * (H_ * B_) +
                                                (size_t)(ks * 64 + kl) * B_ + bbase + half * 8);
            s0 = hs[0]; s1 = hs[1];
        }
#pragma unroll
        for (int c = 0; c < 4; c++) {
            STS4(128 + ks * 64 + c * 16 + kl, s0, s1);
            __syncwarp();
            if (c < 3) {
                const float4 *hs = (const float4 *)(g_HallT + (size_t)t * (H_ * B_) +
                                                    (size_t)(ks * 64 + (c + 1) * 16 + kl) * B_ +
                                                    bbase + half * 8);
                s0 = hs[0]; s1 = hs[1];
            }
            GEMM16(128 + ks * 64 + c * 16);
        }

        // ---- partial writes + reduce ----
        {
            u64 *rp = red + ((size_t)(ks * 8 + bpH * 4) * 16 + hq) * 3;
            rp[0] = a00;  rp[1] = a01;  rp[2] = a02;
            rp[48] = a10; rp[49] = a11; rp[50] = a12;
            rp[96] = a20; rp[97] = a21; rp[98] = a22;
            rp[144] = a30; rp[145] = a31; rp[146] = a32;
        }
        __syncthreads();

        // ---- elementwise per (b_l,h_l) ----
        float p0 = bs0, p1 = bs1, p2 = bs2;
#pragma unroll
        for (int s = 0; s < 8; s++) {
            int base = (((s * 8 + bp) * 16 + h_l) * 3) * 2 + comp;
            p0 += redf[base];
            p1 += redf[base + 2];
            p2 += redf[base + 4];
        }
        float gi = sigmoidf_(p0);
        float go = sigmoidf_(p1);
        float gc = tanhf(p2);
        float c = gi * gc - conv;
        ring[((t & 31) << 8) + rbase] = c;
        float hn = go * tanhf(c);
        g_HallT[((size_t)(t + 1) * H_ + hbase + h_l) * B_ + bbase + b_l] = hn;
        g_Hall[((size_t)(t + 1) * B_ + bbase + b_l) * H_ + hbase + h_l] = hn;
        if (t == T_ - 1)
            dout[(size_t)T_ * B_ * O_ + (size_t)(bbase + b_l) * H_ + hbase + h_l] = hn;

        // ---- arrive (last arriver of the 32-CTA group publishes gen = t+1) ----
        __syncthreads();
        if (tid == 0) {
            unsigned arrived;
            asm volatile("atom.acq_rel.gpu.global.add.u32 %0, [%1], %2;"
                         : "=r"(arrived) : "l"(pcnt), "r"(1u) : "memory");
            if (arrived + 1u == 32u * (unsigned)(t + 1)) {
                asm volatile("st.release.gpu.global.u32 [%0], %1;"
                             :: "l"(pgen), "r"((unsigned)(t + 1)) : "memory");
            }
        }
    }

    // epilogue: hc_last = ring (slot j == hc_last[j] since 480 % 32 == 0)
    {
        const size_t HC0 = (size_t)T_ * B_ * O_ + (size_t)B_ * H_;
#pragma unroll
        for (int j = 0; j < K_; j++)
            dout[HC0 + ((size_t)j * B_ + bbase + b_l) * H_ + hbase + h_l] =
                ring[(j << 8) + b_l * 16 + h_l];
    }
}

// ---------------- launch ----------------
extern "C" void kernel_launch(void* const* d_in, const int* in_sizes, int n_in,
                              void* d_out, int out_size) {
    const float *inputs = (const float *)d_in[0];
    const float *Wi = (const float *)d_in[1];
    const float *bi = (const float *)d_in[2];
    const float *Wo = (const float *)d_in[3];
    const float *bo = (const float *)d_in[4];
    const float *Wc = (const float *)d_in[5];
    const float *bc = (const float *)d_in[6];
    const float *Wout = (const float *)d_in[7];
    const float *bout = (const float *)d_in[8];
    const float *dv = (const float *)d_in[9];
    float *out = (float *)d_out;

    float *pHall = nullptr;
    cudaGetSymbolAddress((void **)&pHall, g_Hall);
    cudaFuncSetAttribute(recurrent_kernel, cudaFuncAttributeMaxDynamicSharedMemorySize,
                         SMEM_BYTES);

    // 1) pack weights / biases / frac-diff weights, zero h_0, reset per-bg barriers
    prep_kernel<<<1280, 256>>>(Wi, bi, Wo, bo, Wc, bc, dv);
    // 2) transpose inputs -> [t][i][b]
    transpose_x<<<T_, 256>>>(inputs);
    // 3) serial recurrence (persistent, per-bg barriered; x-projection fused in)
    recurrent_kernel<<<NCTA, 256, SMEM_BYTES>>>(out);
    // 4) outputs: [T*B,512] @ [512,128] + bias -> d_out[0 : T*B*O)
    gemm_bias<<<dim3((T_ * B_) / 128, O_ / 64), 256>>>(pHall + B_ * H_, Wout, bout, out, O_, H_);
}